// round 10
// baseline (speedup 1.0000x reference)
#include <cuda_runtime.h>
#include <cstdint>

#define IN_F   4096
#define OUT_F  4096
#define PACKED (IN_F / 2)
#define NBLK   (IN_F / 64)

#define BM 128
#define BN 128
#define BK 32
#define NKT (IN_F / BK)             // 128 k-tiles
#define TILE_FLOATS 4096            // 128x32 floats = 16 KB (fragment-ordered)
#define STAGE_BYTES  32768          // A + B
#define STAGES 3
#define SMEM_BYTES (STAGES * STAGE_BYTES)   // 98304 B -> 2 CTA/SM

// Fragment-ordered, tf32-pre-rounded operand scratch.
// A tile (128x32): float idx = (kk*8 + mf)*128 + lane*4 + slot
//   lane = (rr&7)*4 + c, slot = (rr>>3) + 2*hi, m'=mf*16+rr, k'=kk*8+hi*4+c
// B tile (128x32): float idx = (kk*16 + nf)*64 + lane*2 + hi
//   lane = (n'&7)*4 + c, n'=nf*8+(n'&7), k'=kk*8+hi*4+c
__device__ float g_At[(size_t)(8192 / BM) * NKT * TILE_FLOATS];   // 134 MB
__device__ float g_Bt[(size_t)(OUT_F / BN) * NKT * TILE_FLOATS];  //  67 MB

// ---------------------------------------------------------------------------
// Pre-pass 1: dequantize 4-bit codes -> tf32 bits -> fragment-ordered g_Bt.
// Vectorized: one thread = 4 packed bytes (ld.128) -> 8 consecutive scratch
// floats (2x st.128). Element e in a k-octet maps to offset [0,2,4,6,1,3,5,7],
// so store order is {e0,e4,e1,e5},{e2,e6,e3,e7}.
// ---------------------------------------------------------------------------
__global__ void dequant_kernel(const int4* __restrict__ wp4,
                               const float* __restrict__ centroids,
                               const float* __restrict__ scales) {
    __shared__ float cent[16];
    if (threadIdx.x < 16) cent[threadIdx.x] = centroids[threadIdx.x];
    __syncthreads();

    int idx = blockIdx.x * blockDim.x + threadIdx.x;   // over OUT_F * 512
    if (idx >= OUT_F * (PACKED / 4)) return;
    int o = idx >> 9;               // row
    int t = idx & 511;              // int4 index in row; k0 = 8t

    int4 w = wp4[idx];
    float s = scales[o * NBLK + (t >> 3)];   // block = (8t)/64 = t/8

    int b0 = w.x & 255, b1 = w.y & 255, b2 = w.z & 255, b3 = w.w & 255;
    float e0 = cent[b0 >> 4] * s, e1 = cent[b0 & 15] * s;
    float e2 = cent[b1 >> 4] * s, e3 = cent[b1 & 15] * s;
    float e4 = cent[b2 >> 4] * s, e5 = cent[b2 & 15] * s;
    float e6 = cent[b3 >> 4] * s, e7 = cent[b3 & 15] * s;

    uint32_t r0, r1, r2, r3, r4, r5, r6, r7;
    asm("cvt.rna.tf32.f32 %0, %1;" : "=r"(r0) : "f"(e0));
    asm("cvt.rna.tf32.f32 %0, %1;" : "=r"(r1) : "f"(e1));
    asm("cvt.rna.tf32.f32 %0, %1;" : "=r"(r2) : "f"(e2));
    asm("cvt.rna.tf32.f32 %0, %1;" : "=r"(r3) : "f"(e3));
    asm("cvt.rna.tf32.f32 %0, %1;" : "=r"(r4) : "f"(e4));
    asm("cvt.rna.tf32.f32 %0, %1;" : "=r"(r5) : "f"(e5));
    asm("cvt.rna.tf32.f32 %0, %1;" : "=r"(r6) : "f"(e6));
    asm("cvt.rna.tf32.f32 %0, %1;" : "=r"(r7) : "f"(e7));

    int ntile = o >> 7;
    int np = o & 127;
    int kt = t >> 2;                // (8t)/32
    int kk = t & 3;
    int nf = np >> 3;
    int l0 = (np & 7) * 4;

    float* base = g_Bt + (size_t)ntile * (NKT * TILE_FLOATS)
                       + (size_t)kt * TILE_FLOATS + (kk * 16 + nf) * 64 + l0 * 2;
    float4 f4a, f4b;
    f4a.x = __uint_as_float(r0); f4a.y = __uint_as_float(r4);
    f4a.z = __uint_as_float(r1); f4a.w = __uint_as_float(r5);
    f4b.x = __uint_as_float(r2); f4b.y = __uint_as_float(r6);
    f4b.z = __uint_as_float(r3); f4b.w = __uint_as_float(r7);
    *reinterpret_cast<float4*>(base)     = f4a;
    *reinterpret_cast<float4*>(base + 4) = f4b;
}

// ---------------------------------------------------------------------------
// Pre-pass 2: tf32-round X -> fragment-ordered g_At.
// ---------------------------------------------------------------------------
__global__ void retile_x_kernel(const float* __restrict__ X, int M) {
    int t = blockIdx.x * blockDim.x + threadIdx.x;
    if (t >= M * (IN_F / 4)) return;
    int e = t * 4;
    int m = e >> 12;
    int i = e & (IN_F - 1);

    float4 v = *reinterpret_cast<const float4*>(X + (size_t)m * IN_F + i);
    uint32_t t0, t1, t2, t3;
    asm("cvt.rna.tf32.f32 %0, %1;" : "=r"(t0) : "f"(v.x));
    asm("cvt.rna.tf32.f32 %0, %1;" : "=r"(t1) : "f"(v.y));
    asm("cvt.rna.tf32.f32 %0, %1;" : "=r"(t2) : "f"(v.z));
    asm("cvt.rna.tf32.f32 %0, %1;" : "=r"(t3) : "f"(v.w));

    int mtile = m >> 7;
    int mp = m & 127;
    int mf = mp >> 4;
    int rr = mp & 15;
    int kt = i >> 5;
    int kp = i & 31;
    int kk = kp >> 3;
    int hi = (kp & 7) >> 2;
    int lane0 = (rr & 7) * 4;
    int slot = ((rr >> 3) & 1) + 2 * hi;

    float* tile = g_At + (size_t)mtile * (NKT * TILE_FLOATS) + (size_t)kt * TILE_FLOATS;
    int base = (kk * 8 + mf) * 128 + lane0 * 4 + slot;
    tile[base]      = __uint_as_float(t0);
    tile[base + 4]  = __uint_as_float(t1);
    tile[base + 8]  = __uint_as_float(t2);
    tile[base + 12] = __uint_as_float(t3);
}

// ---------------------------------------------------------------------------
// GEMM: 128x128x32 tiles, 8 warps (2x4, warp tile 64x32), mma.sync tf32,
// 2 CTA/SM (4 warps/SMSP for TLP latency hiding). Fragment-ordered SMEM,
// 3-stage cp.async, wait -> barrier -> loads ordering.
// ---------------------------------------------------------------------------
__device__ __forceinline__ void mma_tf32(float* c, const uint32_t* a, const uint32_t* b) {
    asm volatile(
        "mma.sync.aligned.m16n8k8.row.col.f32.tf32.tf32.f32 "
        "{%0,%1,%2,%3}, {%4,%5,%6,%7}, {%8,%9}, {%0,%1,%2,%3};\n"
        : "+f"(c[0]), "+f"(c[1]), "+f"(c[2]), "+f"(c[3])
        : "r"(a[0]), "r"(a[1]), "r"(a[2]), "r"(a[3]),
          "r"(b[0]), "r"(b[1]));
}

__device__ __forceinline__ void load_stage(uint32_t sbase, const float* Asrc,
                                           const float* Bsrc, int kt, int buf, int tid) {
    uint32_t d = sbase + (uint32_t)buf * STAGE_BYTES + (uint32_t)tid * 16;
    const float* pa = Asrc + (size_t)kt * TILE_FLOATS + tid * 4;
    const float* pb = Bsrc + (size_t)kt * TILE_FLOATS + tid * 4;
#pragma unroll
    for (int i = 0; i < 4; i++) {
        asm volatile("cp.async.cg.shared.global [%0], [%1], 16;\n"
                     :: "r"(d + i * 4096), "l"(pa + i * 1024));
        asm volatile("cp.async.cg.shared.global [%0], [%1], 16;\n"
                     :: "r"(d + 16384 + i * 4096), "l"(pb + i * 1024));
    }
}

__global__ void __launch_bounds__(256, 2)
gemm_tf32_kernel(float* __restrict__ Out) {
    extern __shared__ float smem[];

    const int tid  = threadIdx.x;
    const int warp = tid >> 5;
    const int lane = tid & 31;
    const int wm = warp >> 2;              // 0..1 -> M offset wm*64
    const int wn = warp & 3;               // 0..3 -> N offset wn*32

    const float* Ag = g_At + (size_t)blockIdx.y * (NKT * TILE_FLOATS);
    const float* Bg = g_Bt + (size_t)blockIdx.x * (NKT * TILE_FLOATS);

    const uint32_t sbase = (uint32_t)__cvta_generic_to_shared(smem);

    float c[4][4][4];
#pragma unroll
    for (int i = 0; i < 4; i++)
#pragma unroll
        for (int j = 0; j < 4; j++)
#pragma unroll
            for (int k = 0; k < 4; k++) c[i][j][k] = 0.0f;

    load_stage(sbase, Ag, Bg, 0, 0, tid);
    asm volatile("cp.async.commit_group;\n" ::: "memory");
    load_stage(sbase, Ag, Bg, 1, 1, tid);
    asm volatile("cp.async.commit_group;\n" ::: "memory");

    for (int kt = 0; kt < NKT; kt++) {
        asm volatile("cp.async.wait_group 1;\n" ::: "memory");   // my tile-kt copies done
        __syncthreads();                                         // all visible; old buf free

        if (kt + 2 < NKT)
            load_stage(sbase, Ag, Bg, kt + 2, (kt + 2) % STAGES, tid);
        asm volatile("cp.async.commit_group;\n" ::: "memory");

        const float* S  = smem + (size_t)(kt % STAGES) * (STAGE_BYTES / 4);
        const float* A0 = S;
        const float* B0 = S + TILE_FLOATS;

#pragma unroll
        for (int kk = 0; kk < 4; kk++) {
            uint32_t a[4][4];
            uint32_t b[4][2];
#pragma unroll
            for (int ma = 0; ma < 4; ma++) {
                const float4 v = *reinterpret_cast<const float4*>(
                    A0 + (kk * 8 + wm * 4 + ma) * 128 + lane * 4);
                a[ma][0] = __float_as_uint(v.x);
                a[ma][1] = __float_as_uint(v.y);
                a[ma][2] = __float_as_uint(v.z);
                a[ma][3] = __float_as_uint(v.w);
            }
#pragma unroll
            for (int nb = 0; nb < 4; nb++) {
                const float2 v = *reinterpret_cast<const float2*>(
                    B0 + (kk * 16 + wn * 4 + nb) * 64 + lane * 2);
                b[nb][0] = __float_as_uint(v.x);
                b[nb][1] = __float_as_uint(v.y);
            }
#pragma unroll
            for (int ma = 0; ma < 4; ma++)
#pragma unroll
                for (int nb = 0; nb < 4; nb++)
                    mma_tf32(c[ma][nb], a[ma], b[nb]);
        }
    }

    // epilogue
    float* Og = Out + (size_t)blockIdx.y * BM * OUT_F + blockIdx.x * BN;
#pragma unroll
    for (int ma = 0; ma < 4; ma++) {
#pragma unroll
        for (int nb = 0; nb < 4; nb++) {
            int r  = wm * 64 + ma * 16 + (lane >> 2);
            int cc = wn * 32 + nb * 8 + 2 * (lane & 3);
            *reinterpret_cast<float2*>(&Og[(size_t)r * OUT_F + cc]) =
                make_float2(c[ma][nb][0], c[ma][nb][1]);
            *reinterpret_cast<float2*>(&Og[(size_t)(r + 8) * OUT_F + cc]) =
                make_float2(c[ma][nb][2], c[ma][nb][3]);
        }
    }
}

// ---------------------------------------------------------------------------
extern "C" void kernel_launch(void* const* d_in, const int* in_sizes, int n_in,
                              void* d_out, int out_size) {
    const float* x      = (const float*)d_in[0];   // [M, 4096] fp32
    const int*   wp     = (const int*)d_in[1];     // [4096, 2048] int32 bytes
    const float* cent   = (const float*)d_in[2];   // [16]
    const float* scales = (const float*)d_in[3];   // [4096, 64]
    float* out = (float*)d_out;

    const int M = in_sizes[0] / IN_F;              // 8192

    int totalW4 = OUT_F * (PACKED / 4);
    dequant_kernel<<<(totalW4 + 255) / 256, 256>>>(
        reinterpret_cast<const int4*>(wp), cent, scales);

    int totalX4 = M * (IN_F / 4);
    retile_x_kernel<<<(totalX4 + 255) / 256, 256>>>(x, M);

    cudaFuncSetAttribute(gemm_tf32_kernel,
                         cudaFuncAttributeMaxDynamicSharedMemorySize, SMEM_BYTES);
    dim3 grid(OUT_F / BN, M / BM);                 // (32, 64)
    gemm_tf32_kernel<<<grid, 256, SMEM_BYTES>>>(out);
}

// round 11
// speedup vs baseline: 1.1787x; 1.1787x over previous
#include <cuda_runtime.h>
#include <cstdint>

#define IN_F   4096
#define OUT_F  4096
#define PACKED (IN_F / 2)
#define NBLK   (IN_F / 64)

#define BM 128
#define BN 128
#define BK 32
#define NKT (IN_F / BK)             // 128 k-tiles
#define TILE_FLOATS 4096            // 128x32 floats = 16 KB per operand block
#define STAGE_BYTES  32768          // A (16KB) + B (16KB)
#define STAGES 3
#define SMEM_HDR 1024
#define SMEM_BYTES (SMEM_HDR + STAGES * STAGE_BYTES)   // 99328 B -> 2 CTA/SM

// Fragment-ordered, tf32-pre-rounded operand scratch.
// A tile (128x32): float idx = (kk*8 + mf)*128 + lane*4 + slot
//   lane = (rr&7)*4 + c, slot = (rr>>3) + 2*hi, m'=mf*16+rr, k'=kk*8+hi*4+c
// B tile (128x32): float idx = (kk*16 + nf)*64 + lane*2 + hi
//   lane = (n'&7)*4 + c, n'=nf*8+(n'&7), k'=kk*8+hi*4+c
__device__ float g_At[(size_t)(8192 / BM) * NKT * TILE_FLOATS];   // 134 MB
__device__ float g_Bt[(size_t)(OUT_F / BN) * NKT * TILE_FLOATS];  //  67 MB

#define MBAR_INIT(a, c) \
    asm volatile("mbarrier.init.shared.b64 [%0], %1;" :: "r"(a), "r"((uint32_t)(c)) : "memory")
#define MBAR_EXPECT_TX(a, b) \
    asm volatile("mbarrier.arrive.expect_tx.shared.b64 _, [%0], %1;" :: "r"(a), "r"((uint32_t)(b)) : "memory")
#define MBAR_WAIT(a, ph) do {                                                    \
    uint32_t _done = 0;                                                          \
    while (!_done)                                                               \
        asm volatile("{\n\t.reg .pred p;\n\t"                                    \
            "mbarrier.try_wait.parity.shared.b64 p, [%1], %2;\n\t"               \
            "selp.b32 %0, 1, 0, p;\n\t}"                                         \
            : "=r"(_done) : "r"((uint32_t)(a)), "r"((uint32_t)(ph)) : "memory"); \
    } while (0)
#define BULK_G2S(dst, src, bytes, mbar) \
    asm volatile("cp.async.bulk.shared::cluster.global.mbarrier::complete_tx::bytes " \
                 "[%0], [%1], %2, [%3];" \
                 :: "r"((uint32_t)(dst)), "l"(src), "r"((uint32_t)(bytes)), \
                    "r"((uint32_t)(mbar)) : "memory")

// ---------------------------------------------------------------------------
// Pre-pass 1: dequantize 4-bit codes -> tf32 bits -> fragment-ordered g_Bt.
// One thread = 4 packed bytes (ld.128) -> 8 consecutive scratch floats
// (2x st.128). Element e in a k-octet maps to offset [0,2,4,6,1,3,5,7],
// so store order is {e0,e4,e1,e5},{e2,e6,e3,e7}.
// ---------------------------------------------------------------------------
__global__ void dequant_kernel(const int4* __restrict__ wp4,
                               const float* __restrict__ centroids,
                               const float* __restrict__ scales) {
    __shared__ float cent[16];
    if (threadIdx.x < 16) cent[threadIdx.x] = centroids[threadIdx.x];
    __syncthreads();

    int idx = blockIdx.x * blockDim.x + threadIdx.x;   // over OUT_F * 512
    if (idx >= OUT_F * (PACKED / 4)) return;
    int o = idx >> 9;               // row
    int t = idx & 511;              // int4 index in row; k0 = 8t

    int4 w = wp4[idx];
    float s = scales[o * NBLK + (t >> 3)];

    int b0 = w.x & 255, b1 = w.y & 255, b2 = w.z & 255, b3 = w.w & 255;
    float e0 = cent[b0 >> 4] * s, e1 = cent[b0 & 15] * s;
    float e2 = cent[b1 >> 4] * s, e3 = cent[b1 & 15] * s;
    float e4 = cent[b2 >> 4] * s, e5 = cent[b2 & 15] * s;
    float e6 = cent[b3 >> 4] * s, e7 = cent[b3 & 15] * s;

    uint32_t r0, r1, r2, r3, r4, r5, r6, r7;
    asm("cvt.rna.tf32.f32 %0, %1;" : "=r"(r0) : "f"(e0));
    asm("cvt.rna.tf32.f32 %0, %1;" : "=r"(r1) : "f"(e1));
    asm("cvt.rna.tf32.f32 %0, %1;" : "=r"(r2) : "f"(e2));
    asm("cvt.rna.tf32.f32 %0, %1;" : "=r"(r3) : "f"(e3));
    asm("cvt.rna.tf32.f32 %0, %1;" : "=r"(r4) : "f"(e4));
    asm("cvt.rna.tf32.f32 %0, %1;" : "=r"(r5) : "f"(e5));
    asm("cvt.rna.tf32.f32 %0, %1;" : "=r"(r6) : "f"(e6));
    asm("cvt.rna.tf32.f32 %0, %1;" : "=r"(r7) : "f"(e7));

    int ntile = o >> 7;
    int np = o & 127;
    int kt = t >> 2;
    int kk = t & 3;
    int nf = np >> 3;
    int l0 = (np & 7) * 4;

    float* base = g_Bt + (size_t)ntile * (NKT * TILE_FLOATS)
                       + (size_t)kt * TILE_FLOATS + (kk * 16 + nf) * 64 + l0 * 2;
    float4 f4a, f4b;
    f4a.x = __uint_as_float(r0); f4a.y = __uint_as_float(r4);
    f4a.z = __uint_as_float(r1); f4a.w = __uint_as_float(r5);
    f4b.x = __uint_as_float(r2); f4b.y = __uint_as_float(r6);
    f4b.z = __uint_as_float(r3); f4b.w = __uint_as_float(r7);
    *reinterpret_cast<float4*>(base)     = f4a;
    *reinterpret_cast<float4*>(base + 4) = f4b;
}

// ---------------------------------------------------------------------------
// Pre-pass 2: tf32-round X -> fragment-ordered g_At.
// ---------------------------------------------------------------------------
__global__ void retile_x_kernel(const float* __restrict__ X, int M) {
    int t = blockIdx.x * blockDim.x + threadIdx.x;
    if (t >= M * (IN_F / 4)) return;
    int e = t * 4;
    int m = e >> 12;
    int i = e & (IN_F - 1);

    float4 v = *reinterpret_cast<const float4*>(X + (size_t)m * IN_F + i);
    uint32_t t0, t1, t2, t3;
    asm("cvt.rna.tf32.f32 %0, %1;" : "=r"(t0) : "f"(v.x));
    asm("cvt.rna.tf32.f32 %0, %1;" : "=r"(t1) : "f"(v.y));
    asm("cvt.rna.tf32.f32 %0, %1;" : "=r"(t2) : "f"(v.z));
    asm("cvt.rna.tf32.f32 %0, %1;" : "=r"(t3) : "f"(v.w));

    int mtile = m >> 7;
    int mp = m & 127;
    int mf = mp >> 4;
    int rr = mp & 15;
    int kt = i >> 5;
    int kp = i & 31;
    int kk = kp >> 3;
    int hi = (kp & 7) >> 2;
    int lane0 = (rr & 7) * 4;
    int slot = ((rr >> 3) & 1) + 2 * hi;

    float* tile = g_At + (size_t)mtile * (NKT * TILE_FLOATS) + (size_t)kt * TILE_FLOATS;
    int base = (kk * 8 + mf) * 128 + lane0 * 4 + slot;
    tile[base]      = __uint_as_float(t0);
    tile[base + 4]  = __uint_as_float(t1);
    tile[base + 8]  = __uint_as_float(t2);
    tile[base + 12] = __uint_as_float(t3);
}

// ---------------------------------------------------------------------------
// GEMM: 128x128x32 tiles, 4 warps (2x2, warp tile 64x64), mma.sync tf32,
// 2 CTA/SM. Fragment-ordered SMEM + register double-buffered fragments.
// Producer: single thread issues cp.async.bulk per stage (2 instrs instead
// of 2048 LDGSTS), completion via mbarrier expect_tx.
// ---------------------------------------------------------------------------
__device__ __forceinline__ void mma_tf32(float* c, const uint32_t* a, const uint32_t* b) {
    asm volatile(
        "mma.sync.aligned.m16n8k8.row.col.f32.tf32.tf32.f32 "
        "{%0,%1,%2,%3}, {%4,%5,%6,%7}, {%8,%9}, {%0,%1,%2,%3};\n"
        : "+f"(c[0]), "+f"(c[1]), "+f"(c[2]), "+f"(c[3])
        : "r"(a[0]), "r"(a[1]), "r"(a[2]), "r"(a[3]),
          "r"(b[0]), "r"(b[1]));
}

__device__ __forceinline__ void load_frags(uint32_t a[4][4], uint32_t b[8][2],
                                           const float* A0, const float* B0,
                                           int kk, int wm, int wn, int lane) {
#pragma unroll
    for (int ma = 0; ma < 4; ma++) {
        const float4 v = *reinterpret_cast<const float4*>(
            A0 + (kk * 8 + wm * 4 + ma) * 128 + lane * 4);
        a[ma][0] = __float_as_uint(v.x);
        a[ma][1] = __float_as_uint(v.y);
        a[ma][2] = __float_as_uint(v.z);
        a[ma][3] = __float_as_uint(v.w);
    }
#pragma unroll
    for (int nb = 0; nb < 8; nb++) {
        const float2 v = *reinterpret_cast<const float2*>(
            B0 + (kk * 16 + wn * 8 + nb) * 64 + lane * 2);
        b[nb][0] = __float_as_uint(v.x);
        b[nb][1] = __float_as_uint(v.y);
    }
}

__global__ void __launch_bounds__(128, 2)
gemm_tf32_kernel(float* __restrict__ Out) {
    extern __shared__ float smem[];

    const int tid  = threadIdx.x;
    const int warp = tid >> 5;
    const int lane = tid & 31;
    const int wm = warp >> 1;              // 0..1 -> M offset wm*64
    const int wn = warp & 1;               // 0..1 -> N offset wn*64

    const float* Ag = g_At + (size_t)blockIdx.y * (NKT * TILE_FLOATS);
    const float* Bg = g_Bt + (size_t)blockIdx.x * (NKT * TILE_FLOATS);

    const uint32_t sbase = (uint32_t)__cvta_generic_to_shared(smem);
    const uint32_t mb0   = sbase;                 // full[s] at +s*8
    const uint32_t st0   = sbase + SMEM_HDR;
    const float*   stf   = smem + SMEM_HDR / 4;   // stage floats base

    if (tid == 0) {
#pragma unroll
        for (int s = 0; s < STAGES; s++) MBAR_INIT(mb0 + s * 8, 1);
    }
    __syncthreads();

    if (tid == 0) {
#pragma unroll
        for (int p = 0; p < 2; p++) {
            MBAR_EXPECT_TX(mb0 + p * 8, STAGE_BYTES);
            BULK_G2S(st0 + p * STAGE_BYTES,         Ag + (size_t)p * TILE_FLOATS, 16384, mb0 + p * 8);
            BULK_G2S(st0 + p * STAGE_BYTES + 16384, Bg + (size_t)p * TILE_FLOATS, 16384, mb0 + p * 8);
        }
    }

    float c[4][8][4];
#pragma unroll
    for (int i = 0; i < 4; i++)
#pragma unroll
        for (int j = 0; j < 8; j++)
#pragma unroll
            for (int k = 0; k < 4; k++) c[i][j][k] = 0.0f;

    uint32_t a[2][4][4];
    uint32_t b[2][8][2];

    for (int kt = 0; kt < NKT; kt++) {
        const int s = kt % STAGES;
        MBAR_WAIT(mb0 + s * 8, (kt / STAGES) & 1);   // tile kt data arrived
        __syncthreads();                             // all done reading buf (kt+2)%3

        const float* S  = stf + (size_t)s * (STAGE_BYTES / 4);
        const float* A0 = S;
        const float* B0 = S + TILE_FLOATS;

        // prefetch fragment group 0, then let thread 0 kick off tile kt+2
        load_frags(a[0], b[0], A0, B0, 0, wm, wn, lane);

        if (tid == 0 && kt + 2 < NKT) {
            const int sn = (kt + 2) % STAGES;
            MBAR_EXPECT_TX(mb0 + sn * 8, STAGE_BYTES);
            BULK_G2S(st0 + sn * STAGE_BYTES,         Ag + (size_t)(kt + 2) * TILE_FLOATS, 16384, mb0 + sn * 8);
            BULK_G2S(st0 + sn * STAGE_BYTES + 16384, Bg + (size_t)(kt + 2) * TILE_FLOATS, 16384, mb0 + sn * 8);
        }

#pragma unroll
        for (int kk = 0; kk < 4; kk++) {
            const int cur = kk & 1;
            if (kk < 3)
                load_frags(a[cur ^ 1], b[cur ^ 1], A0, B0, kk + 1, wm, wn, lane);
#pragma unroll
            for (int ma = 0; ma < 4; ma++)
#pragma unroll
                for (int nb = 0; nb < 8; nb++)
                    mma_tf32(c[ma][nb], a[cur][ma], b[cur][nb]);
        }
    }

    // epilogue
    float* Og = Out + (size_t)blockIdx.y * BM * OUT_F + blockIdx.x * BN;
#pragma unroll
    for (int ma = 0; ma < 4; ma++) {
#pragma unroll
        for (int nb = 0; nb < 8; nb++) {
            int r  = wm * 64 + ma * 16 + (lane >> 2);
            int cc = wn * 64 + nb * 8 + 2 * (lane & 3);
            *reinterpret_cast<float2*>(&Og[(size_t)r * OUT_F + cc]) =
                make_float2(c[ma][nb][0], c[ma][nb][1]);
            *reinterpret_cast<float2*>(&Og[(size_t)(r + 8) * OUT_F + cc]) =
                make_float2(c[ma][nb][2], c[ma][nb][3]);
        }
    }
}

// ---------------------------------------------------------------------------
extern "C" void kernel_launch(void* const* d_in, const int* in_sizes, int n_in,
                              void* d_out, int out_size) {
    const float* x      = (const float*)d_in[0];   // [M, 4096] fp32
    const int*   wp     = (const int*)d_in[1];     // [4096, 2048] int32 bytes
    const float* cent   = (const float*)d_in[2];   // [16]
    const float* scales = (const float*)d_in[3];   // [4096, 64]
    float* out = (float*)d_out;

    const int M = in_sizes[0] / IN_F;              // 8192

    int totalW4 = OUT_F * (PACKED / 4);
    dequant_kernel<<<(totalW4 + 255) / 256, 256>>>(
        reinterpret_cast<const int4*>(wp), cent, scales);

    int totalX4 = M * (IN_F / 4);
    retile_x_kernel<<<(totalX4 + 255) / 256, 256>>>(x, M);

    cudaFuncSetAttribute(gemm_tf32_kernel,
                         cudaFuncAttributeMaxDynamicSharedMemorySize, SMEM_BYTES);
    dim3 grid(OUT_F / BN, M / BM);                 // (32, 64)
    gemm_tf32_kernel<<<grid, 128, SMEM_BYTES>>>(out);
}

// round 12
// speedup vs baseline: 2.2887x; 1.9418x over previous
#include <cuda_runtime.h>
#include <cuda_fp16.h>
#include <cstdint>

#define IN_F   4096
#define OUT_F  4096
#define PACKED (IN_F / 2)
#define NBLK   (IN_F / 64)

#define BM 128
#define BN 128
#define BK 64                        // fp16: 128x64 halfs = 16 KB per block
#define NKT (IN_F / BK)              // 64 k-tiles
#define TILE_U32 4096                // uint32s per operand block (16 KB)
#define STAGE_BYTES  32768           // A (16KB) + B (16KB)
#define STAGES 3
#define SMEM_HDR 1024
#define SMEM_BYTES (SMEM_HDR + STAGES * STAGE_BYTES)   // 99328 B -> 2 CTA/SM

// Fragment-ordered fp16 operand scratch (each uint32 = half2{k, k+1}).
// A block (128m x 64k): u32 idx = (kk*8 + mf)*128 + lane*4 + slot
//   lane = (rr&7)*4 + kpair, slot = (rr>>3) + 2*hi   (m=mf*16+rr, k=kk*16+hi*8+kpair*2)
// B block (128n x 64k): u32 idx = (kk*16 + nf)*64 + lane*2 + hi
//   lane = (n&7)*4 + kpair                            (n=nf*8+(n&7))
__device__ uint32_t g_At[(size_t)(8192 / BM) * NKT * TILE_U32];   // 67 MB
__device__ uint32_t g_Bt[(size_t)(OUT_F / BN) * NKT * TILE_U32];  // 33.5 MB

#define MBAR_INIT(a, c) \
    asm volatile("mbarrier.init.shared.b64 [%0], %1;" :: "r"(a), "r"((uint32_t)(c)) : "memory")
#define MBAR_EXPECT_TX(a, b) \
    asm volatile("mbarrier.arrive.expect_tx.shared.b64 _, [%0], %1;" :: "r"(a), "r"((uint32_t)(b)) : "memory")
#define MBAR_WAIT(a, ph) do {                                                    \
    uint32_t _done = 0;                                                          \
    while (!_done)                                                               \
        asm volatile("{\n\t.reg .pred p;\n\t"                                    \
            "mbarrier.try_wait.parity.shared.b64 p, [%1], %2;\n\t"               \
            "selp.b32 %0, 1, 0, p;\n\t}"                                         \
            : "=r"(_done) : "r"((uint32_t)(a)), "r"((uint32_t)(ph)) : "memory"); \
    } while (0)
#define BULK_G2S(dst, src, bytes, mbar) \
    asm volatile("cp.async.bulk.shared::cluster.global.mbarrier::complete_tx::bytes " \
                 "[%0], [%1], %2, [%3];" \
                 :: "r"((uint32_t)(dst)), "l"(src), "r"((uint32_t)(bytes)), \
                    "r"((uint32_t)(mbar)) : "memory")

__device__ __forceinline__ uint32_t pack_h2(float lo, float hi) {
    half2 h = __floats2half2_rn(lo, hi);
    return *reinterpret_cast<uint32_t*>(&h);
}

// ---------------------------------------------------------------------------
// Pre-pass 1: dequantize 4-bit codes -> fp16 -> fragment-ordered g_Bt.
// Thread t of row o handles bytes 4t..4t+3 = k elements 8t..8t+7 (one hi-half
// of one kk group). Writes 4 half2 regs at lanes kpair=0..3.
// ---------------------------------------------------------------------------
__global__ void dequant_kernel(const int4* __restrict__ wp4,
                               const float* __restrict__ centroids,
                               const float* __restrict__ scales) {
    __shared__ float cent[16];
    if (threadIdx.x < 16) cent[threadIdx.x] = centroids[threadIdx.x];
    __syncthreads();

    int idx = blockIdx.x * blockDim.x + threadIdx.x;   // over OUT_F * 512
    if (idx >= OUT_F * (PACKED / 4)) return;
    int o = idx >> 9;               // row (n)
    int t = idx & 511;              // int4 index; k0 = 8t

    int4 w = wp4[idx];
    float s = scales[o * NBLK + (t >> 3)];

    int b0 = w.x & 255, b1 = w.y & 255, b2 = w.z & 255, b3 = w.w & 255;
    float e0 = cent[b0 >> 4] * s, e1 = cent[b0 & 15] * s;
    float e2 = cent[b1 >> 4] * s, e3 = cent[b1 & 15] * s;
    float e4 = cent[b2 >> 4] * s, e5 = cent[b2 & 15] * s;
    float e6 = cent[b3 >> 4] * s, e7 = cent[b3 & 15] * s;

    int ntile = o >> 7;
    int np = o & 127;
    int kt = t >> 3;                // (8t)/64
    int kk = (t & 7) >> 1;          // 16-k group
    int hi = t & 1;                 // low/high 8-k half
    int nf = np >> 3;
    int l0 = (np & 7) * 4;

    uint32_t* base = g_Bt + (size_t)ntile * (NKT * TILE_U32)
                          + (size_t)kt * TILE_U32 + (kk * 16 + nf) * 64 + l0 * 2 + hi;
    base[0] = pack_h2(e0, e1);      // kpair 0
    base[2] = pack_h2(e2, e3);      // kpair 1
    base[4] = pack_h2(e4, e5);      // kpair 2
    base[6] = pack_h2(e6, e7);      // kpair 3
}

// ---------------------------------------------------------------------------
// Pre-pass 2: fp16-round X -> fragment-ordered g_At.
// Thread handles 4 consecutive floats (2 k-pairs, same slot, lanes c0,c0+1).
// ---------------------------------------------------------------------------
__global__ void retile_x_kernel(const float* __restrict__ X, int M) {
    int t = blockIdx.x * blockDim.x + threadIdx.x;
    if (t >= M * (IN_F / 4)) return;
    int e = t * 4;
    int m = e >> 12;
    int i = e & (IN_F - 1);

    float4 v = *reinterpret_cast<const float4*>(X + (size_t)m * IN_F + i);

    int mtile = m >> 7;
    int mp = m & 127;
    int mf = mp >> 4;
    int rr = mp & 15;
    int kt = i >> 6;
    int kp = i & 63;
    int kk = kp >> 4;
    int kw = kp & 15;
    int hi = kw >> 3;
    int c0 = (kw & 7) >> 1;         // 0 or 2
    int s  = ((rr >> 3) & 1) + 2 * hi;
    int l0 = (rr & 7) * 4 + c0;

    uint32_t* base = g_At + (size_t)mtile * (NKT * TILE_U32) + (size_t)kt * TILE_U32
                          + (kk * 8 + mf) * 128 + l0 * 4 + s;
    base[0] = pack_h2(v.x, v.y);
    base[4] = pack_h2(v.z, v.w);    // next lane -> +4 u32
}

// ---------------------------------------------------------------------------
// GEMM: 128x128x64 tiles, 4 warps (2x2, warp tile 64x64), mma.sync fp16
// m16n8k16 fp32-accum, 2 CTA/SM. Bulk-async producer + mbarrier ring,
// register double-buffered fragments.
// ---------------------------------------------------------------------------
__device__ __forceinline__ void mma_fp16(float* c, const uint32_t* a, const uint32_t* b) {
    asm volatile(
        "mma.sync.aligned.m16n8k16.row.col.f32.f16.f16.f32 "
        "{%0,%1,%2,%3}, {%4,%5,%6,%7}, {%8,%9}, {%0,%1,%2,%3};\n"
        : "+f"(c[0]), "+f"(c[1]), "+f"(c[2]), "+f"(c[3])
        : "r"(a[0]), "r"(a[1]), "r"(a[2]), "r"(a[3]),
          "r"(b[0]), "r"(b[1]));
}

__device__ __forceinline__ void load_frags(uint32_t a[4][4], uint32_t b[8][2],
                                           const uint32_t* A0, const uint32_t* B0,
                                           int kk, int wm, int wn, int lane) {
#pragma unroll
    for (int ma = 0; ma < 4; ma++) {
        const uint4 v = *reinterpret_cast<const uint4*>(
            A0 + (kk * 8 + wm * 4 + ma) * 128 + lane * 4);
        a[ma][0] = v.x; a[ma][1] = v.y; a[ma][2] = v.z; a[ma][3] = v.w;
    }
#pragma unroll
    for (int nb = 0; nb < 8; nb++) {
        const uint2 v = *reinterpret_cast<const uint2*>(
            B0 + (kk * 16 + wn * 8 + nb) * 64 + lane * 2);
        b[nb][0] = v.x; b[nb][1] = v.y;
    }
}

__global__ void __launch_bounds__(128, 2)
gemm_fp16_kernel(float* __restrict__ Out) {
    extern __shared__ uint32_t smem[];

    const int tid  = threadIdx.x;
    const int warp = tid >> 5;
    const int lane = tid & 31;
    const int wm = warp >> 1;              // 0..1 -> M offset wm*64
    const int wn = warp & 1;               // 0..1 -> N offset wn*64

    const uint32_t* Ag = g_At + (size_t)blockIdx.y * (NKT * TILE_U32);
    const uint32_t* Bg = g_Bt + (size_t)blockIdx.x * (NKT * TILE_U32);

    const uint32_t sbase = (uint32_t)__cvta_generic_to_shared(smem);
    const uint32_t mb0   = sbase;                 // full[s] at +s*8
    const uint32_t st0   = sbase + SMEM_HDR;
    const uint32_t* stf  = smem + SMEM_HDR / 4;

    if (tid == 0) {
#pragma unroll
        for (int s = 0; s < STAGES; s++) MBAR_INIT(mb0 + s * 8, 1);
    }
    __syncthreads();

    if (tid == 0) {
#pragma unroll
        for (int p = 0; p < 2; p++) {
            MBAR_EXPECT_TX(mb0 + p * 8, STAGE_BYTES);
            BULK_G2S(st0 + p * STAGE_BYTES,         Ag + (size_t)p * TILE_U32, 16384, mb0 + p * 8);
            BULK_G2S(st0 + p * STAGE_BYTES + 16384, Bg + (size_t)p * TILE_U32, 16384, mb0 + p * 8);
        }
    }

    float c[4][8][4];
#pragma unroll
    for (int i = 0; i < 4; i++)
#pragma unroll
        for (int j = 0; j < 8; j++)
#pragma unroll
            for (int k = 0; k < 4; k++) c[i][j][k] = 0.0f;

    uint32_t a[2][4][4];
    uint32_t b[2][8][2];

    for (int kt = 0; kt < NKT; kt++) {
        const int s = kt % STAGES;
        MBAR_WAIT(mb0 + s * 8, (kt / STAGES) & 1);   // tile kt arrived
        __syncthreads();                             // all done reading buf (kt+2)%3

        const uint32_t* A0 = stf + (size_t)s * (STAGE_BYTES / 4);
        const uint32_t* B0 = A0 + TILE_U32;

        load_frags(a[0], b[0], A0, B0, 0, wm, wn, lane);

        if (tid == 0 && kt + 2 < NKT) {
            const int sn = (kt + 2) % STAGES;
            MBAR_EXPECT_TX(mb0 + sn * 8, STAGE_BYTES);
            BULK_G2S(st0 + sn * STAGE_BYTES,         Ag + (size_t)(kt + 2) * TILE_U32, 16384, mb0 + sn * 8);
            BULK_G2S(st0 + sn * STAGE_BYTES + 16384, Bg + (size_t)(kt + 2) * TILE_U32, 16384, mb0 + sn * 8);
        }

#pragma unroll
        for (int kk = 0; kk < 4; kk++) {
            const int cur = kk & 1;
            if (kk < 3)
                load_frags(a[cur ^ 1], b[cur ^ 1], A0, B0, kk + 1, wm, wn, lane);
#pragma unroll
            for (int ma = 0; ma < 4; ma++)
#pragma unroll
                for (int nb = 0; nb < 8; nb++)
                    mma_fp16(c[ma][nb], a[cur][ma], b[cur][nb]);
        }
    }

    // epilogue (D fragment layout identical to tf32 path)
    float* Og = Out + (size_t)blockIdx.y * BM * OUT_F + blockIdx.x * BN;
#pragma unroll
    for (int ma = 0; ma < 4; ma++) {
#pragma unroll
        for (int nb = 0; nb < 8; nb++) {
            int r  = wm * 64 + ma * 16 + (lane >> 2);
            int cc = wn * 64 + nb * 8 + 2 * (lane & 3);
            *reinterpret_cast<float2*>(&Og[(size_t)r * OUT_F + cc]) =
                make_float2(c[ma][nb][0], c[ma][nb][1]);
            *reinterpret_cast<float2*>(&Og[(size_t)(r + 8) * OUT_F + cc]) =
                make_float2(c[ma][nb][2], c[ma][nb][3]);
        }
    }
}

// ---------------------------------------------------------------------------
extern "C" void kernel_launch(void* const* d_in, const int* in_sizes, int n_in,
                              void* d_out, int out_size) {
    const float* x      = (const float*)d_in[0];   // [M, 4096] fp32
    const int*   wp     = (const int*)d_in[1];     // [4096, 2048] int32 bytes
    const float* cent   = (const float*)d_in[2];   // [16]
    const float* scales = (const float*)d_in[3];   // [4096, 64]
    float* out = (float*)d_out;

    const int M = in_sizes[0] / IN_F;              // 8192

    int totalW4 = OUT_F * (PACKED / 4);
    dequant_kernel<<<(totalW4 + 255) / 256, 256>>>(
        reinterpret_cast<const int4*>(wp), cent, scales);

    int totalX4 = M * (IN_F / 4);
    retile_x_kernel<<<(totalX4 + 255) / 256, 256>>>(x, M);

    cudaFuncSetAttribute(gemm_fp16_kernel,
                         cudaFuncAttributeMaxDynamicSharedMemorySize, SMEM_BYTES);
    dim3 grid(OUT_F / BN, M / BM);                 // (32, 64)
    gemm_fp16_kernel<<<grid, 128, SMEM_BYTES>>>(out);
}